// round 2
// baseline (speedup 1.0000x reference)
#include <cuda_runtime.h>
#include <stdint.h>

// Problem constants (fixed by setup_inputs)
#define B_SZ     32
#define C_SZ     384
#define T_SZ     1024
#define MAXLEN   8192
#define CH_OUT   (C_SZ + 2)          // 386
#define MAX_DUR  10000

// Scratch (allocation-free rule: device globals)
__device__ int g_ends[B_SZ][T_SZ];   // inclusive cumsum of clipped durations
__device__ int g_dval[B_SZ][T_SZ];   // clipped durations
__device__ int g_tok [B_SZ][MAXLEN]; // token index per output position, -1 = invalid

// ---------------------------------------------------------------------------
// Kernel 1: per-batch scan + token-map scatter + tail fill + mel_len
// One block per batch, 1024 threads (== T).
// ---------------------------------------------------------------------------
__global__ __launch_bounds__(1024) void prep_kernel(
    const int* __restrict__ duration,   // [B, T] int32 (JAX x64 disabled)
    float* __restrict__ out, long long out_size)
{
    const int b   = blockIdx.x;
    const int tid = threadIdx.x;

    __shared__ int s[T_SZ];

    // clip(|d|, 1, MAX_DUR)
    int dv = duration[b * T_SZ + tid];
    int ad = dv < 0 ? -dv : dv;
    int d  = ad < 1 ? 1 : (ad > MAX_DUR ? MAX_DUR : ad);

    // Hillis-Steele inclusive scan over 1024 elements
    s[tid] = d;
    __syncthreads();
    #pragma unroll
    for (int off = 1; off < T_SZ; off <<= 1) {
        int v = (tid >= off) ? s[tid - off] : 0;
        __syncthreads();
        s[tid] += v;
        __syncthreads();
    }

    int end   = s[tid];
    int start = end - d;
    int total = s[T_SZ - 1];

    g_ends[b][tid] = end;
    g_dval[b][tid] = d;

    // Scatter token index to its output span (spans are disjoint)
    int e = end < MAXLEN ? end : MAXLEN;
    for (int p = start; p < e; ++p)
        g_tok[b][p] = tid;

    // Tail fill: invalid positions -> -1
    for (int p = total + tid; p < MAXLEN; p += blockDim.x)
        g_tok[b][p] = -1;

    // mel_len (second output), appended after out[0]; guarded by out_size
    if (tid == 0) {
        long long base = (long long)B_SZ * CH_OUT * MAXLEN;
        if (base + b < out_size)
            out[base + b] = (float)total;
    }
}

// ---------------------------------------------------------------------------
// Kernel 2: streaming expand-gather.
// grid = (MAXLEN/(4*256)=8, CH_OUT=386, B=32), 256 threads, 4 positions/thread.
// ---------------------------------------------------------------------------
__global__ __launch_bounds__(256) void expand_kernel(
    const float* __restrict__ x,   // [B, C, T]
    float* __restrict__ out)       // [B, CH_OUT, MAXLEN] (+ mel_len tail)
{
    const int b  = blockIdx.z;
    const int ch = blockIdx.y;
    const int pos0 = (blockIdx.x * 256 + threadIdx.x) * 4;

    const int4 t4 = *reinterpret_cast<const int4*>(&g_tok[b][pos0]);

    float4 v;
    if (ch < C_SZ) {
        const float* __restrict__ xrow = x + ((long long)b * C_SZ + ch) * T_SZ;
        v.x = (t4.x >= 0) ? __ldg(&xrow[t4.x]) : 0.0f;
        v.y = (t4.y >= 0) ? __ldg(&xrow[t4.y]) : 0.0f;
        v.z = (t4.z >= 0) ? __ldg(&xrow[t4.z]) : 0.0f;
        v.w = (t4.w >= 0) ? __ldg(&xrow[t4.w]) : 0.0f;
    } else if (ch == C_SZ) {
        // idx_in = pos - start[tok] = pos - (ends[tok] - d[tok])
        v.x = (t4.x >= 0) ? (float)(pos0 + 0 - (g_ends[b][t4.x] - g_dval[b][t4.x])) : 0.0f;
        v.y = (t4.y >= 0) ? (float)(pos0 + 1 - (g_ends[b][t4.y] - g_dval[b][t4.y])) : 0.0f;
        v.z = (t4.z >= 0) ? (float)(pos0 + 2 - (g_ends[b][t4.z] - g_dval[b][t4.z])) : 0.0f;
        v.w = (t4.w >= 0) ? (float)(pos0 + 3 - (g_ends[b][t4.w] - g_dval[b][t4.w])) : 0.0f;
    } else {
        // length = d[tok]
        v.x = (t4.x >= 0) ? (float)g_dval[b][t4.x] : 0.0f;
        v.y = (t4.y >= 0) ? (float)g_dval[b][t4.y] : 0.0f;
        v.z = (t4.z >= 0) ? (float)g_dval[b][t4.z] : 0.0f;
        v.w = (t4.w >= 0) ? (float)g_dval[b][t4.w] : 0.0f;
    }

    *reinterpret_cast<float4*>(
        &out[((long long)b * CH_OUT + ch) * MAXLEN + pos0]) = v;
}

// ---------------------------------------------------------------------------
extern "C" void kernel_launch(void* const* d_in, const int* in_sizes, int n_in,
                              void* d_out, int out_size)
{
    const float* x   = (const float*)d_in[0];
    const int*   dur = (const int*)d_in[1];
    float*       out = (float*)d_out;

    prep_kernel<<<B_SZ, 1024>>>(dur, out, (long long)out_size);

    dim3 grid(MAXLEN / (4 * 256), CH_OUT, B_SZ);
    expand_kernel<<<grid, 256>>>(x, out);
}